// round 4
// baseline (speedup 1.0000x reference)
#include <cuda_runtime.h>
#include <math.h>

#define NODES 512
#define S     8
#define DIN   768
#define NN    4096                 /* NODES * S */
#define NB    64                   /* persistent blocks per matrix */
#define TPB   512
#define NWARPS (NB * (TPB/32))     /* warps per matrix */

/* ------------------------------------------------------------------ */
/* Static device scratch (no allocations allowed)                      */
/* ------------------------------------------------------------------ */
__device__ float         g_X[2][NODES][S];
__device__ unsigned char g_adj[2][NODES][NODES];
__device__ double        g_A[2][(size_t)NN * NN];     /* 2 x 128 MB */
__device__ double        g_y[2][NN];
__device__ double        g_norm2[2][NN];
__device__ double        g_vty[2][NN];
__device__ double        g_diag[2][NN];
__device__ double        g_offd[2][NN];
__device__ float         g_eig[2][NN];
__device__ unsigned int  g_count[2];
__device__ unsigned int  g_gen[2];

/* ------------------------------------------------------------------ */
/* software grid barrier over NB blocks of one matrix                  */
/* ------------------------------------------------------------------ */
__device__ __forceinline__ void gridbar(int mat)
{
    __threadfence();                 /* release writes (gpu scope => L1 inval) */
    __syncthreads();
    if (threadIdx.x == 0) {
        volatile unsigned int* genp = &g_gen[mat];
        unsigned int old = *genp;
        if (atomicAdd(&g_count[mat], 1u) == (unsigned)(NB - 1)) {
            atomicExch(&g_count[mat], 0u);
            __threadfence();
            atomicExch(&g_gen[mat], old + 1u);
        } else {
            while (*genp == old) __nanosleep(64);
        }
        __threadfence();             /* invalidate L1 before consuming */
    }
    __syncthreads();
}

/* ------------------------------------------------------------------ */
/* K1: X = cloud @ W^T for both clouds; also zero adjacency            */
/* ------------------------------------------------------------------ */
__global__ __launch_bounds__(256) void k_proj(const float* __restrict__ q,
                                              const float* __restrict__ pos,
                                              const float* __restrict__ neg,
                                              const float* __restrict__ W)
{
    int b     = blockIdx.x;
    int cloud = b >> 9;
    int row   = b & 511;
    const float* src = (row < 256) ? (q + (size_t)row * DIN)
                                   : ((cloud == 0 ? pos : neg) + (size_t)(row - 256) * DIN);
    __shared__ float sm[256];
    int t = threadIdx.x;
    int c = t & 7;
    int g = t >> 3;
    float acc = 0.f;
    for (int j = g; j < DIN; j += 32)
        acc += src[j] * W[c * DIN + j];
    sm[t] = acc;
    __syncthreads();
    for (int off = 128; off >= 8; off >>= 1) {
        if (t < off) sm[t] += sm[t + off];
        __syncthreads();
    }
    if (t < 8) g_X[cloud][row][t] = sm[t];

    int* adj32 = (int*)g_adj;
    int  base  = b * 128;
    for (int i = t; i < 128; i += 256) adj32[base + i] = 0;
}

/* ------------------------------------------------------------------ */
/* K2: KNN (K=5) + symmetric adjacency scatter                          */
/* ------------------------------------------------------------------ */
__global__ __launch_bounds__(256) void k_knn()
{
    int b     = blockIdx.x;
    int cloud = b >> 9;
    int i     = b & 511;
    __shared__ float sX[NODES][S];
    __shared__ float sd[NODES];
    int t = threadIdx.x;
    for (int idx = t; idx < NODES * S; idx += 256)
        ((float*)sX)[idx] = ((const float*)g_X[cloud])[idx];
    __syncthreads();
    for (int j = t; j < NODES; j += 256) {
        float d2 = 0.f;
        #pragma unroll
        for (int c = 0; c < S; c++) {
            float d = sX[j][c] - sX[i][c];
            d2 += d * d;
        }
        sd[j] = (j == i) ? 3.4e38f : d2;
    }
    __syncthreads();
    if (t == 0) {
        for (int p = 0; p < 5; p++) {     /* strict < == stable argsort */
            float best = 3.4e38f;
            int   bj   = 0;
            for (int j = 0; j < NODES; j++)
                if (sd[j] < best) { best = sd[j]; bj = j; }
            sd[bj] = 3.4e38f;
            g_adj[cloud][i][bj] = 1;
            g_adj[cloud][bj][i] = 1;
        }
    }
}

/* ------------------------------------------------------------------ */
/* K3: assemble dense L (fp64, exactly symmetric) from 8x8 blocks       */
/* ------------------------------------------------------------------ */
__global__ __launch_bounds__(256) void k_assemble()
{
    int i     = blockIdx.x;
    int cloud = blockIdx.y;
    __shared__ float         sX[NODES][S];
    __shared__ unsigned char sadj[NODES];
    __shared__ double        sdiag[64];
    int t = threadIdx.x;
    for (int idx = t; idx < NODES * S; idx += 256)
        ((float*)sX)[idx] = ((const float*)g_X[cloud])[idx];
    for (int idx = t; idx < NODES; idx += 256)
        sadj[idx] = g_adj[cloud][i][idx];
    __syncthreads();

    if (t < 64) {
        int    a  = t >> 3, bb = t & 7;
        double acc = 0.0;
        int    deg = 0;
        for (int k = 0; k < NODES; k++) {
            if (!sadj[k]) continue;
            deg++;
            if (k < i) {
                double d[S];
                double dn2 = 0.0;
                #pragma unroll
                for (int c = 0; c < S; c++) {
                    d[c] = (double)sX[i][c] - (double)sX[k][c];
                    dn2 += d[c] * d[c];
                }
                double dn    = sqrt(dn2) + 1e-12;
                double alpha = fmin(dn, 1.0);
                double coef  = (2.0 * alpha - alpha * alpha) / (dn * dn);
                acc -= coef * d[a] * d[bb];
            }
        }
        if (a == bb) acc += (double)deg;
        sdiag[t] = acc;
    }
    __syncthreads();

    int   a    = t >> 5;
    int   lane = t & 31;
    double* rowp = g_A[cloud] + (size_t)(8 * i + a) * NN;
    for (int cb = 0; cb < NN; cb += 32) {
        int col = cb + lane;
        int j   = col >> 3, bb = col & 7;
        double val = 0.0;
        if (j == i) {
            val = sdiag[a * 8 + bb];
        } else if (sadj[j]) {
            double d[S];
            double dn2 = 0.0;
            #pragma unroll
            for (int c = 0; c < S; c++) {
                d[c] = (double)sX[j][c] - (double)sX[i][c];
                dn2 += d[c] * d[c];
            }
            double dn    = sqrt(dn2) + 1e-12;
            double alpha = fmin(dn, 1.0);
            double sc    = alpha / (dn * dn);
            val = sc * d[a] * d[bb] - (a == bb ? 1.0 : 0.0);
        }
        rowp[col] = val;
    }
}

/* ------------------------------------------------------------------ */
/* K4: persistent fp64 Householder tridiagonalization (both matrices)   */
/* grid 2*NB blocks, TPB threads; dynamic smem = 2*NN doubles           */
/* ------------------------------------------------------------------ */
__global__ __launch_bounds__(TPB) void k_tridiag()
{
    extern __shared__ double dsm[];
    double* sv = dsm;
    double* sw = dsm + NN;
    __shared__ double sred[TPB / 32];

    int mat  = blockIdx.x / NB;
    int blk  = blockIdx.x % NB;
    int tid  = threadIdx.x;
    int lane = tid & 31;
    int wid  = tid >> 5;
    int gw   = blk * (TPB / 32) + wid;      /* global warp id within mat */
    double* A = g_A[mat];

    /* phase 0: zero per-step accumulators */
    for (int i = blk * TPB + tid; i < NN; i += NB * TPB) {
        g_norm2[mat][i] = 0.0;
        g_vty[mat][i]   = 0.0;
    }
    gridbar(mat);

    /* phase 1: ssq of A[0][2..NN-1] -> g_norm2[0] */
    {
        double p = 0.0;
        for (int j = blk * TPB + tid; j < NN - 2; j += NB * TPB) {
            double x = A[2 + j];
            p += x * x;
        }
        #pragma unroll
        for (int o = 16; o; o >>= 1) p += __shfl_xor_sync(~0u, p, o);
        if (lane == 0) sred[wid] = p;
        __syncthreads();
        if (tid == 0) {
            double s = 0.0;
            for (int i = 0; i < TPB / 32; i++) s += sred[i];
            atomicAdd(&g_norm2[mat][0], s);
        }
    }
    gridbar(mat);

    for (int k = 0; k < NN - 2; ++k) {
        int m = NN - 1 - k;
        const double* rowk = A + (size_t)k * NN + (k + 1);
        double alpha = rowk[0];
        double n2    = g_norm2[mat][k];
        double tau, beta, scale;
        if (n2 == 0.0) { tau = 0.0; beta = alpha; scale = 0.0; }
        else {
            beta  = -copysign(sqrt(alpha * alpha + n2), alpha);
            tau   = (beta - alpha) / beta;
            scale = 1.0 / (alpha - beta);
        }
        if (blk == 0 && tid == 0) g_offd[mat][k] = beta;

        /* v into smem */
        for (int c = tid; c < m; c += TPB)
            sv[c] = (c == 0) ? 1.0 : rowk[c] * scale;
        __syncthreads();

        /* SYMV y = A_trail * v ; fused partial v^T y */
        double* At = A + (size_t)(k + 1) * NN + (k + 1);
        double vty_p = 0.0;
        for (int r = gw; r < m; r += NWARPS) {
            const double* Ar = At + (size_t)r * NN;
            double a0 = 0.0, a1 = 0.0, a2 = 0.0, a3 = 0.0;
            int c = lane;
            for (; c + 96 < m; c += 128) {
                a0 += Ar[c]      * sv[c];
                a1 += Ar[c + 32] * sv[c + 32];
                a2 += Ar[c + 64] * sv[c + 64];
                a3 += Ar[c + 96] * sv[c + 96];
            }
            for (; c < m; c += 32) a0 += Ar[c] * sv[c];
            double acc = (a0 + a1) + (a2 + a3);
            #pragma unroll
            for (int o = 16; o; o >>= 1) acc += __shfl_xor_sync(~0u, acc, o);
            if (lane == 0) {
                g_y[mat][r] = acc;
                vty_p += sv[r] * acc;
            }
        }
        if (lane == 0) sred[wid] = vty_p;
        __syncthreads();
        if (tid == 0) {
            double s = 0.0;
            for (int i = 0; i < TPB / 32; i++) s += sred[i];
            atomicAdd(&g_vty[mat][k], s);
        }
        gridbar(mat);

        /* rank-2 update A -= v w^T + w v^T ; fuse next-step norm2 (row 0) */
        double vty = g_vty[mat][k];
        double c2  = 0.5 * tau * tau * vty;
        for (int c = tid; c < m; c += TPB)
            sw[c] = tau * g_y[mat][c] - c2 * sv[c];
        __syncthreads();

        double n2p = 0.0;
        for (int r = gw; r < m; r += NWARPS) {
            double vr = sv[r], wr = sw[r];
            double* Ar = At + (size_t)r * NN;
            if (r == 0) {
                for (int c = lane; c < m; c += 32) {
                    double a = Ar[c] - vr * sw[c] - wr * sv[c];
                    Ar[c] = a;
                    if (c >= 1) n2p += a * a;
                }
            } else {
                int c = lane;
                for (; c + 96 < m; c += 128) {
                    Ar[c]      -= vr * sw[c]      + wr * sv[c];
                    Ar[c + 32] -= vr * sw[c + 32] + wr * sv[c + 32];
                    Ar[c + 64] -= vr * sw[c + 64] + wr * sv[c + 64];
                    Ar[c + 96] -= vr * sw[c + 96] + wr * sv[c + 96];
                }
                for (; c < m; c += 32)
                    Ar[c] -= vr * sw[c] + wr * sv[c];
            }
        }
        if (gw == 0) {
            #pragma unroll
            for (int o = 16; o; o >>= 1) n2p += __shfl_xor_sync(~0u, n2p, o);
            if (lane == 0) g_norm2[mat][k + 1] = n2p;   /* single writer */
        }
        gridbar(mat);
    }

    /* collect diagonal + last off-diagonal */
    for (int i = blk * TPB + tid; i < NN; i += NB * TPB)
        g_diag[mat][i] = A[(size_t)i * NN + i];
    if (blk == 0 && tid == 0) {
        g_offd[mat][NN - 2] = A[(size_t)(NN - 2) * NN + (NN - 1)];
        g_offd[mat][NN - 1] = 0.0;
    }
}

/* ------------------------------------------------------------------ */
/* K5: Sturm bisection (fp32), all 4096 eigenvalues per matrix          */
/* ------------------------------------------------------------------ */
__global__ __launch_bounds__(256) void k_bisect()
{
    int mat = blockIdx.y;
    __shared__ float sa[NN];
    __shared__ float sb2[NN];
    __shared__ float red[256];
    __shared__ float s_gl, s_gu, s_pm;
    int t = threadIdx.x;
    for (int i = t; i < NN; i += 256) {
        sa[i] = (float)g_diag[mat][i];
        float b = (i < NN - 1) ? (float)g_offd[mat][i] : 0.f;
        sb2[i] = b * b;
    }
    __syncthreads();

    float lo = 3.4e38f, hi = -3.4e38f, mb2 = 0.f;
    for (int i = t; i < NN; i += 256) {
        float bl = (i > 0)      ? sqrtf(sb2[i - 1]) : 0.f;
        float br = (i < NN - 1) ? sqrtf(sb2[i])     : 0.f;
        lo  = fminf(lo, sa[i] - bl - br);
        hi  = fmaxf(hi, sa[i] + bl + br);
        mb2 = fmaxf(mb2, sb2[i]);
    }
    red[t] = lo;  __syncthreads();
    for (int off = 128; off; off >>= 1) { if (t < off) red[t] = fminf(red[t], red[t + off]); __syncthreads(); }
    if (t == 0) s_gl = red[0];
    __syncthreads();
    red[t] = hi;  __syncthreads();
    for (int off = 128; off; off >>= 1) { if (t < off) red[t] = fmaxf(red[t], red[t + off]); __syncthreads(); }
    if (t == 0) s_gu = red[0];
    __syncthreads();
    red[t] = mb2; __syncthreads();
    for (int off = 128; off; off >>= 1) { if (t < off) red[t] = fmaxf(red[t], red[t + off]); __syncthreads(); }
    if (t == 0) s_pm = red[0];
    __syncthreads();

    float span   = s_gu - s_gl;
    float gl     = s_gl - 0.01f * span - 1e-3f;
    float gu     = s_gu + 0.01f * span + 1e-3f;
    float pivmin = fmaxf(s_pm * 1.2e-38f, 1.2e-38f);

    int tgt = blockIdx.x * 256 + t;
    float blo = gl, bhi = gu;
    for (int it = 0; it < 32; it++) {
        float mid = 0.5f * (blo + bhi);
        if (mid <= blo || mid >= bhi) break;
        float d   = sa[0] - mid;
        int   cnt = (d < 0.f);
        #pragma unroll 8
        for (int i = 1; i < NN; i++) {
            d = (sa[i] - mid) - __fdividef(sb2[i - 1], d);
            if (fabsf(d) < pivmin) d = -pivmin;
            cnt += (d < 0.f);
        }
        if (cnt > tgt) bhi = mid; else blo = mid;
    }
    g_eig[mat][tgt] = 0.5f * (blo + bhi);
}

/* ------------------------------------------------------------------ */
/* K6: spectral gaps -> triplet loss scalar (fp64)                      */
/* ------------------------------------------------------------------ */
__global__ __launch_bounds__(256) void k_final(float* __restrict__ out)
{
    __shared__ double sn[256], sd_[256];
    double gap[2];
    int t = threadIdx.x;
    for (int mat = 0; mat < 2; mat++) {
        double accn = 0.0, accd = 0.0;
        for (int i = t; i < NN; i += 256) {
            double lam = (double)fmaxf(g_eig[mat][i], 0.f);
            double z   = (lam - 1e-4) / 0.01;
            double s   = 1.0 / (1.0 + exp(-z));
            accn += lam * s;
            accd += s;
        }
        sn[t] = accn; sd_[t] = accd;
        __syncthreads();
        for (int off = 128; off; off >>= 1) {
            if (t < off) { sn[t] += sn[t + off]; sd_[t] += sd_[t + off]; }
            __syncthreads();
        }
        gap[mat] = sn[0] / (sd_[0] + 1e-12);
        __syncthreads();
    }
    if (t == 0) {
        double trip = gap[0] - gap[1] + 0.5;
        if (trip < 0.0) trip = 0.0;
        out[0] = (float)(trip + 0.1 * gap[0]);
    }
}

/* ------------------------------------------------------------------ */
extern "C" void kernel_launch(void* const* d_in, const int* in_sizes, int n_in,
                              void* d_out, int out_size)
{
    const float* q   = (const float*)d_in[0];
    const float* pos = (const float*)d_in[1];
    const float* neg = (const float*)d_in[2];
    const float* W   = (const float*)d_in[3];
    (void)in_sizes; (void)n_in; (void)out_size;

    cudaFuncSetAttribute((const void*)k_tridiag,
                         cudaFuncAttributeMaxDynamicSharedMemorySize,
                         (int)(2 * NN * sizeof(double)));

    k_proj<<<1024, 256>>>(q, pos, neg, W);
    k_knn<<<1024, 256>>>();
    {
        dim3 ga(512, 2);
        k_assemble<<<ga, 256>>>();
    }
    k_tridiag<<<2 * NB, TPB, 2 * NN * sizeof(double)>>>();
    {
        dim3 gb(16, 2);
        k_bisect<<<gb, 256>>>();
    }
    k_final<<<1, 256>>>((float*)d_out);
}

// round 6
// speedup vs baseline: 1.0587x; 1.0587x over previous
#include <cuda_runtime.h>
#include <math.h>

#define NODES 512
#define S     8
#define DIN   768
#define NN    4096                 /* NODES * S */
#define NB    128                  /* persistent blocks per matrix */
#define TPB   512
#define NWT   (NB * (TPB / 32))    /* warps per matrix = 2048 */

/* ------------------------------------------------------------------ */
/* Static device scratch (no allocations allowed)                      */
/* ------------------------------------------------------------------ */
__device__ float         g_X[2][NODES][S];
__device__ unsigned char g_adj[2][NODES][NODES];
__device__ double        g_A[2][(size_t)NN * NN];     /* 2 x 128 MB */
__device__ double        g_y[2][NN];
__device__ double        g_vty[2][NN];
__device__ double        g_diag[2][NN];
__device__ double        g_offd[2][NN];
__device__ float         g_eig[2][NN];
__device__ unsigned int  g_count[2];
__device__ unsigned int  g_gen[2];

/* ------------------------------------------------------------------ */
/* software grid barrier over NB blocks of one matrix                  */
/* ------------------------------------------------------------------ */
__device__ __forceinline__ void gridbar(int mat)
{
    __threadfence();                 /* release writes (gpu scope) */
    __syncthreads();
    if (threadIdx.x == 0) {
        volatile unsigned int* genp = &g_gen[mat];
        unsigned int old = *genp;
        if (atomicAdd(&g_count[mat], 1u) == (unsigned)(NB - 1)) {
            atomicExch(&g_count[mat], 0u);
            __threadfence();
            atomicExch(&g_gen[mat], old + 1u);
        } else {
            while (*genp == old) __nanosleep(64);
        }
        __threadfence();             /* invalidate L1 before consuming */
    }
    __syncthreads();
}

/* ------------------------------------------------------------------ */
/* K1: X = cloud @ W^T for both clouds; also zero adjacency            */
/* ------------------------------------------------------------------ */
__global__ __launch_bounds__(256) void k_proj(const float* __restrict__ q,
                                              const float* __restrict__ pos,
                                              const float* __restrict__ neg,
                                              const float* __restrict__ W)
{
    int b     = blockIdx.x;
    int cloud = b >> 9;
    int row   = b & 511;
    const float* src = (row < 256) ? (q + (size_t)row * DIN)
                                   : ((cloud == 0 ? pos : neg) + (size_t)(row - 256) * DIN);
    __shared__ float sm[256];
    int t = threadIdx.x;
    int c = t & 7;
    int g = t >> 3;
    float acc = 0.f;
    for (int j = g; j < DIN; j += 32)
        acc += src[j] * W[c * DIN + j];
    sm[t] = acc;
    __syncthreads();
    for (int off = 128; off >= 8; off >>= 1) {
        if (t < off) sm[t] += sm[t + off];
        __syncthreads();
    }
    if (t < 8) g_X[cloud][row][t] = sm[t];

    int* adj32 = (int*)g_adj;
    int  base  = b * 128;
    for (int i = t; i < 128; i += 256) adj32[base + i] = 0;
}

/* ------------------------------------------------------------------ */
/* K2: KNN (K=5) + symmetric adjacency scatter                          */
/* ------------------------------------------------------------------ */
__global__ __launch_bounds__(256) void k_knn()
{
    int b     = blockIdx.x;
    int cloud = b >> 9;
    int i     = b & 511;
    __shared__ float sX[NODES][S];
    __shared__ float sd[NODES];
    int t = threadIdx.x;
    for (int idx = t; idx < NODES * S; idx += 256)
        ((float*)sX)[idx] = ((const float*)g_X[cloud])[idx];
    __syncthreads();
    for (int j = t; j < NODES; j += 256) {
        float d2 = 0.f;
        #pragma unroll
        for (int c = 0; c < S; c++) {
            float d = sX[j][c] - sX[i][c];
            d2 += d * d;
        }
        sd[j] = (j == i) ? 3.4e38f : d2;
    }
    __syncthreads();
    if (t == 0) {
        for (int p = 0; p < 5; p++) {     /* strict < == stable argsort */
            float best = 3.4e38f;
            int   bj   = 0;
            for (int j = 0; j < NODES; j++)
                if (sd[j] < best) { best = sd[j]; bj = j; }
            sd[bj] = 3.4e38f;
            g_adj[cloud][i][bj] = 1;
            g_adj[cloud][bj][i] = 1;
        }
    }
}

/* ------------------------------------------------------------------ */
/* K3: assemble dense L (fp64, exactly symmetric) from 8x8 blocks       */
/* ------------------------------------------------------------------ */
__global__ __launch_bounds__(256) void k_assemble()
{
    int i     = blockIdx.x;
    int cloud = blockIdx.y;
    __shared__ float         sX[NODES][S];
    __shared__ unsigned char sadj[NODES];
    __shared__ double        sdiag[64];
    int t = threadIdx.x;
    for (int idx = t; idx < NODES * S; idx += 256)
        ((float*)sX)[idx] = ((const float*)g_X[cloud])[idx];
    for (int idx = t; idx < NODES; idx += 256)
        sadj[idx] = g_adj[cloud][i][idx];
    __syncthreads();

    if (t < 64) {
        int    a  = t >> 3, bb = t & 7;
        double acc = 0.0;
        int    deg = 0;
        for (int k = 0; k < NODES; k++) {
            if (!sadj[k]) continue;
            deg++;
            if (k < i) {
                double d[S];
                double dn2 = 0.0;
                #pragma unroll
                for (int c = 0; c < S; c++) {
                    d[c] = (double)sX[i][c] - (double)sX[k][c];
                    dn2 += d[c] * d[c];
                }
                double dn    = sqrt(dn2) + 1e-12;
                double alpha = fmin(dn, 1.0);
                double coef  = (2.0 * alpha - alpha * alpha) / (dn * dn);
                acc -= coef * d[a] * d[bb];
            }
        }
        if (a == bb) acc += (double)deg;
        sdiag[t] = acc;
    }
    __syncthreads();

    int   a    = t >> 5;
    int   lane = t & 31;
    double* rowp = g_A[cloud] + (size_t)(8 * i + a) * NN;
    for (int cb = 0; cb < NN; cb += 32) {
        int col = cb + lane;
        int j   = col >> 3, bb = col & 7;
        double val = 0.0;
        if (j == i) {
            val = sdiag[a * 8 + bb];
        } else if (sadj[j]) {
            double d[S];
            double dn2 = 0.0;
            #pragma unroll
            for (int c = 0; c < S; c++) {
                d[c] = (double)sX[j][c] - (double)sX[i][c];
                dn2 += d[c] * d[c];
            }
            double dn    = sqrt(dn2) + 1e-12;
            double alpha = fmin(dn, 1.0);
            double sc    = alpha / (dn * dn);
            val = sc * d[a] * d[bb] - (a == bb ? 1.0 : 0.0);
        }
        rowp[col] = val;
    }
}

/* ------------------------------------------------------------------ */
/* K4: persistent fused fp64 Householder tridiagonalization             */
/* grid 2*NB blocks, TPB threads; dynamic smem = 3*NN doubles           */
/* Per step: ONE fused pass (rank-2 update + next SYMV), ONE barrier.   */
/* ------------------------------------------------------------------ */
__global__ __launch_bounds__(TPB, 2) void k_tridiag()
{
    extern __shared__ double dsm[];
    double* sv  = dsm;            /* v_j                         */
    double* sw  = dsm + NN;       /* w_j                         */
    double* svn = dsm + 2 * NN;   /* virtual row j+1 -> v_{j+1}  */
    __shared__ double sred[TPB / 32];
    __shared__ double s_alpha, s_norm2;

    int mat  = blockIdx.x / NB;
    int blk  = blockIdx.x % NB;
    int tid  = threadIdx.x;
    int lane = tid & 31;
    int wid  = tid >> 5;
    int gw   = blk * (TPB / 32) + wid;
    double* A = g_A[mat];

    /* zero vty slots */
    for (int i = blk * TPB + tid; i < NN; i += NB * TPB)
        g_vty[mat][i] = 0.0;
    gridbar(mat);

    /* ---------------- init (reflector 0 setup) ---------------- */
    for (int t = tid; t < NN; t += TPB) svn[t] = A[t];    /* row 0 */
    __syncthreads();
    {
        double p = 0.0;
        for (int t = tid; t < NN; t += TPB)
            if (t >= 2) p += svn[t] * svn[t];
        #pragma unroll
        for (int o = 16; o; o >>= 1) p += __shfl_xor_sync(~0u, p, o);
        if (lane == 0) sred[wid] = p;
        __syncthreads();
        if (tid == 0) {
            double s = 0.0;
            for (int i = 0; i < TPB / 32; i++) s += sred[i];
            s_norm2 = s;
            s_alpha = svn[1];
            if (blk == 0) g_diag[mat][0] = svn[0];
        }
        __syncthreads();
        double a2  = s_alpha, n22 = s_norm2;
        double sc2 = (n22 == 0.0) ? 0.0
                   : 1.0 / (a2 + copysign(sqrt(a2 * a2 + n22), a2));
        for (int t = tid; t < NN; t += TPB)
            if (t >= 2) svn[t] *= sc2;
        if (tid == 0) { svn[1] = 1.0; svn[0] = 0.0; }
        __syncthreads();
    }
    /* y_0 = A(1..,1..) * v_0 ; vty_0 */
    {
        double vtyp = 0.0;
        for (int q = 1 + gw; q < NN; q += NWT) {
            const double* Ar = A + (size_t)q * NN;
            double y = 0.0;
            int t = lane;
            for (; t + 96 < NN; t += 128) {
                y += Ar[t]      * svn[t]      + Ar[t + 32] * svn[t + 32]
                   + Ar[t + 64] * svn[t + 64] + Ar[t + 96] * svn[t + 96];
            }
            for (; t < NN; t += 32) y += Ar[t] * svn[t];
            #pragma unroll
            for (int o = 16; o; o >>= 1) y += __shfl_xor_sync(~0u, y, o);
            if (lane == 0) {
                g_y[mat][q - 1] = y;
                vtyp += svn[q] * y;
            }
        }
        if (lane == 0) sred[wid] = vtyp;
        __syncthreads();
        if (tid == 0) {
            double s = 0.0;
            for (int i = 0; i < TPB / 32; i++) s += sred[i];
            atomicAdd(&g_vty[mat][0], s);
        }
        __syncthreads();
        for (int t = tid; t < NN - 1; t += TPB) sv[t] = svn[t + 1];
    }
    gridbar(mat);

    /* ---------------- main loop, 1 barrier/step ---------------- */
    for (int j = 0; j + 2 < NN; ++j) {
        int m = NN - 1 - j;

        /* (a) reflector-j scalars (bitwise identical across blocks) */
        double alpha = s_alpha, n2 = s_norm2;
        double vty = g_vty[mat][j];
        double tau, beta;
        if (n2 == 0.0) { tau = 0.0; beta = alpha; }
        else {
            beta = -copysign(sqrt(alpha * alpha + n2), alpha);
            tau  = (beta - alpha) / beta;
        }
        if (blk == 0 && tid == 0) g_offd[mat][j] = beta;
        double c2 = 0.5 * tau * tau * vty;

        /* (b) w_j = tau*y - c2*v */
        const double* yg = g_y[mat];
        for (int t = tid; t < m; t += TPB)
            sw[t] = tau * yg[t] - c2 * sv[t];
        __syncthreads();

        /* (c) virtual update of row j+1 */
        {
            const double* rj1 = A + (size_t)(j + 1) * NN + (j + 1);
            double v0 = sv[0], w0 = sw[0];
            for (int t = tid; t < m; t += TPB)
                svn[t] = rj1[t] - v0 * sw[t] - w0 * sv[t];
        }
        __syncthreads();

        /* (d) reflector-(j+1) scalars from virtual row */
        {
            double p = 0.0;
            for (int t = tid; t < m; t += TPB)
                if (t >= 2) p += svn[t] * svn[t];
            #pragma unroll
            for (int o = 16; o; o >>= 1) p += __shfl_xor_sync(~0u, p, o);
            if (lane == 0) sred[wid] = p;
            __syncthreads();
            if (tid == 0) {
                double s = 0.0;
                for (int i = 0; i < TPB / 32; i++) s += sred[i];
                s_norm2 = s;
                s_alpha = svn[1];
                if (blk == 0) g_diag[mat][j + 1] = svn[0];
            }
            __syncthreads();
        }

        /* (e) build v_{j+1} in svn (svn[t] = v_{j+1}[t-1], svn[0]=0) */
        {
            double a2  = s_alpha, n22 = s_norm2;
            double sc2 = (n22 == 0.0) ? 0.0
                       : 1.0 / (a2 + copysign(sqrt(a2 * a2 + n22), a2));
            for (int t = tid; t < m; t += TPB)
                if (t >= 2) svn[t] *= sc2;
            if (tid == 0) { svn[1] = 1.0; svn[0] = 0.0; }
            __syncthreads();
        }

        /* (f) fused sweep: rank-2 update of rows j+2.. and dot with v_{j+1} */
        {
            double vtyp = 0.0;
            for (int q = 1 + gw; q < m; q += NWT) {
                double vr = sv[q], wr = sw[q];
                double* Ar = A + (size_t)(j + 1 + q) * NN + (j + 1);
                double y = 0.0;
                int t = lane;
                for (; t + 96 < m; t += 128) {
                    double a0 = Ar[t]      - vr * sw[t]      - wr * sv[t];
                    double a1 = Ar[t + 32] - vr * sw[t + 32] - wr * sv[t + 32];
                    double b0 = Ar[t + 64] - vr * sw[t + 64] - wr * sv[t + 64];
                    double b1 = Ar[t + 96] - vr * sw[t + 96] - wr * sv[t + 96];
                    Ar[t]      = a0;
                    Ar[t + 32] = a1;
                    Ar[t + 64] = b0;
                    Ar[t + 96] = b1;
                    y += a0 * svn[t]      + a1 * svn[t + 32]
                       + b0 * svn[t + 64] + b1 * svn[t + 96];
                }
                for (; t < m; t += 32) {
                    double a = Ar[t] - vr * sw[t] - wr * sv[t];
                    Ar[t] = a;
                    y += a * svn[t];
                }
                #pragma unroll
                for (int o = 16; o; o >>= 1) y += __shfl_xor_sync(~0u, y, o);
                if (lane == 0) {
                    g_y[mat][q - 1] = y;
                    vtyp += svn[q] * y;
                }
            }
            if (lane == 0) sred[wid] = vtyp;
            __syncthreads();
            if (tid == 0) {
                double s = 0.0;
                for (int i = 0; i < TPB / 32; i++) s += sred[i];
                atomicAdd(&g_vty[mat][j + 1], s);
            }
            __syncthreads();
        }

        /* (g) carry v_{j+1} into sv (shift by one) */
        for (int t = tid; t < m - 1; t += TPB) sv[t] = svn[t + 1];
        gridbar(mat);
    }

    /* tail */
    if (blk == 0 && tid == 0) {
        g_offd[mat][NN - 2] = s_alpha;          /* final off-diagonal */
        g_offd[mat][NN - 1] = 0.0;
        g_diag[mat][NN - 1] = A[(size_t)(NN - 1) * NN + (NN - 1)];
    }
}

/* ------------------------------------------------------------------ */
/* K5: Sturm bisection (fp32), all 4096 eigenvalues per matrix          */
/* ------------------------------------------------------------------ */
__global__ __launch_bounds__(256) void k_bisect()
{
    int mat = blockIdx.y;
    __shared__ float sa[NN];
    __shared__ float sb2[NN];
    __shared__ float red[256];
    __shared__ float s_gl, s_gu, s_pm;
    int t = threadIdx.x;
    for (int i = t; i < NN; i += 256) {
        sa[i] = (float)g_diag[mat][i];
        float b = (i < NN - 1) ? (float)g_offd[mat][i] : 0.f;
        sb2[i] = b * b;
    }
    __syncthreads();

    float lo = 3.4e38f, hi = -3.4e38f, mb2 = 0.f;
    for (int i = t; i < NN; i += 256) {
        float bl = (i > 0)      ? sqrtf(sb2[i - 1]) : 0.f;
        float br = (i < NN - 1) ? sqrtf(sb2[i])     : 0.f;
        lo  = fminf(lo, sa[i] - bl - br);
        hi  = fmaxf(hi, sa[i] + bl + br);
        mb2 = fmaxf(mb2, sb2[i]);
    }
    red[t] = lo;  __syncthreads();
    for (int off = 128; off; off >>= 1) { if (t < off) red[t] = fminf(red[t], red[t + off]); __syncthreads(); }
    if (t == 0) s_gl = red[0];
    __syncthreads();
    red[t] = hi;  __syncthreads();
    for (int off = 128; off; off >>= 1) { if (t < off) red[t] = fmaxf(red[t], red[t + off]); __syncthreads(); }
    if (t == 0) s_gu = red[0];
    __syncthreads();
    red[t] = mb2; __syncthreads();
    for (int off = 128; off; off >>= 1) { if (t < off) red[t] = fmaxf(red[t], red[t + off]); __syncthreads(); }
    if (t == 0) s_pm = red[0];
    __syncthreads();

    float span   = s_gu - s_gl;
    float gl     = s_gl - 0.01f * span - 1e-3f;
    float gu     = s_gu + 0.01f * span + 1e-3f;
    float pivmin = fmaxf(s_pm * 1.2e-38f, 1.2e-38f);

    int tgt = blockIdx.x * 256 + t;
    float blo = gl, bhi = gu;
    for (int it = 0; it < 32; it++) {
        float mid = 0.5f * (blo + bhi);
        if (mid <= blo || mid >= bhi) break;
        float d   = sa[0] - mid;
        int   cnt = (d < 0.f);
        #pragma unroll 8
        for (int i = 1; i < NN; i++) {
            d = (sa[i] - mid) - __fdividef(sb2[i - 1], d);
            if (fabsf(d) < pivmin) d = -pivmin;
            cnt += (d < 0.f);
        }
        if (cnt > tgt) bhi = mid; else blo = mid;
    }
    g_eig[mat][tgt] = 0.5f * (blo + bhi);
}

/* ------------------------------------------------------------------ */
/* K6: spectral gaps -> triplet loss scalar (fp64)                      */
/* ------------------------------------------------------------------ */
__global__ __launch_bounds__(256) void k_final(float* __restrict__ out)
{
    __shared__ double sn[256], sd_[256];
    double gap[2];
    int t = threadIdx.x;
    for (int mat = 0; mat < 2; mat++) {
        double accn = 0.0, accd = 0.0;
        for (int i = t; i < NN; i += 256) {
            double lam = (double)fmaxf(g_eig[mat][i], 0.f);
            double z   = (lam - 1e-4) / 0.01;
            double s   = 1.0 / (1.0 + exp(-z));
            accn += lam * s;
            accd += s;
        }
        sn[t] = accn; sd_[t] = accd;
        __syncthreads();
        for (int off = 128; off; off >>= 1) {
            if (t < off) { sn[t] += sn[t + off]; sd_[t] += sd_[t + off]; }
            __syncthreads();
        }
        gap[mat] = sn[0] / (sd_[0] + 1e-12);
        __syncthreads();
    }
    if (t == 0) {
        double trip = gap[0] - gap[1] + 0.5;
        if (trip < 0.0) trip = 0.0;
        out[0] = (float)(trip + 0.1 * gap[0]);
    }
}

/* ------------------------------------------------------------------ */
extern "C" void kernel_launch(void* const* d_in, const int* in_sizes, int n_in,
                              void* d_out, int out_size)
{
    const float* q   = (const float*)d_in[0];
    const float* pos = (const float*)d_in[1];
    const float* neg = (const float*)d_in[2];
    const float* W   = (const float*)d_in[3];
    (void)in_sizes; (void)n_in; (void)out_size;

    cudaFuncSetAttribute((const void*)k_tridiag,
                         cudaFuncAttributeMaxDynamicSharedMemorySize,
                         (int)(3 * NN * sizeof(double)));

    k_proj<<<1024, 256>>>(q, pos, neg, W);
    k_knn<<<1024, 256>>>();
    {
        dim3 ga(512, 2);
        k_assemble<<<ga, 256>>>();
    }
    k_tridiag<<<2 * NB, TPB, 3 * NN * sizeof(double)>>>();
    {
        dim3 gb(16, 2);
        k_bisect<<<gb, 256>>>();
    }
    k_final<<<1, 256>>>((float*)d_out);
}

// round 7
// speedup vs baseline: 2.4458x; 2.3101x over previous
#include <cuda_runtime.h>
#include <math.h>

#define NODES 512
#define S     8
#define DIN   768
#define NN    4096                 /* NODES * S */
#define NB    128                  /* persistent blocks per matrix */
#define TPB   512
#define NWT   (NB * (TPB / 32))    /* warps per matrix = 2048 */

/* Kahan step, rounding-locked (fast-math-proof) */
#define KH(s, c, p) do {                                 \
    float _y = __fsub_rn((p), (c));                      \
    float _t = __fadd_rn((s), _y);                       \
    (c) = __fsub_rn(__fsub_rn(_t, (s)), _y);             \
    (s) = _t;                                            \
} while (0)

/* ------------------------------------------------------------------ */
/* Static device scratch (no allocations allowed)                      */
/* ------------------------------------------------------------------ */
__device__ float         g_X[2][NODES][S];
__device__ unsigned char g_adj[2][NODES][NODES];
__device__ float2        g_A[2][(size_t)NN * NN];     /* (hi,lo) compensated fp32 */
__device__ float         g_y[2][NN];
__device__ double        g_vty[2][NN];
__device__ double        g_diag[2][NN];
__device__ double        g_offd[2][NN];
__device__ float         g_eig[2][NN];
__device__ unsigned int  g_count[2];
__device__ unsigned int  g_gen[2];

/* ------------------------------------------------------------------ */
/* software grid barrier over NB blocks of one matrix                  */
/* ------------------------------------------------------------------ */
__device__ __forceinline__ void gridbar(int mat)
{
    __threadfence();
    __syncthreads();
    if (threadIdx.x == 0) {
        volatile unsigned int* genp = &g_gen[mat];
        unsigned int old = *genp;
        if (atomicAdd(&g_count[mat], 1u) == (unsigned)(NB - 1)) {
            atomicExch(&g_count[mat], 0u);
            __threadfence();
            atomicExch(&g_gen[mat], old + 1u);
        } else {
            while (*genp == old) __nanosleep(64);
        }
        __threadfence();
    }
    __syncthreads();
}

/* ------------------------------------------------------------------ */
/* K1: X = cloud @ W^T ; zero adjacency                                */
/* ------------------------------------------------------------------ */
__global__ __launch_bounds__(256) void k_proj(const float* __restrict__ q,
                                              const float* __restrict__ pos,
                                              const float* __restrict__ neg,
                                              const float* __restrict__ W)
{
    int b     = blockIdx.x;
    int cloud = b >> 9;
    int row   = b & 511;
    const float* src = (row < 256) ? (q + (size_t)row * DIN)
                                   : ((cloud == 0 ? pos : neg) + (size_t)(row - 256) * DIN);
    __shared__ float sm[256];
    int t = threadIdx.x;
    int c = t & 7;
    int g = t >> 3;
    float acc = 0.f;
    for (int j = g; j < DIN; j += 32)
        acc += src[j] * W[c * DIN + j];
    sm[t] = acc;
    __syncthreads();
    for (int off = 128; off >= 8; off >>= 1) {
        if (t < off) sm[t] += sm[t + off];
        __syncthreads();
    }
    if (t < 8) g_X[cloud][row][t] = sm[t];

    int* adj32 = (int*)g_adj;
    int  base  = b * 128;
    for (int i = t; i < 128; i += 256) adj32[base + i] = 0;
}

/* ------------------------------------------------------------------ */
/* K2: KNN (K=5) + symmetric adjacency                                  */
/* ------------------------------------------------------------------ */
__global__ __launch_bounds__(256) void k_knn()
{
    int b     = blockIdx.x;
    int cloud = b >> 9;
    int i     = b & 511;
    __shared__ float sX[NODES][S];
    __shared__ float sd[NODES];
    int t = threadIdx.x;
    for (int idx = t; idx < NODES * S; idx += 256)
        ((float*)sX)[idx] = ((const float*)g_X[cloud])[idx];
    __syncthreads();
    for (int j = t; j < NODES; j += 256) {
        float d2 = 0.f;
        #pragma unroll
        for (int c = 0; c < S; c++) {
            float d = sX[j][c] - sX[i][c];
            d2 += d * d;
        }
        sd[j] = (j == i) ? 3.4e38f : d2;
    }
    __syncthreads();
    if (t == 0) {
        for (int p = 0; p < 5; p++) {
            float best = 3.4e38f;
            int   bj   = 0;
            for (int j = 0; j < NODES; j++)
                if (sd[j] < best) { best = sd[j]; bj = j; }
            sd[bj] = 3.4e38f;
            g_adj[cloud][i][bj] = 1;
            g_adj[cloud][bj][i] = 1;
        }
    }
}

/* ------------------------------------------------------------------ */
/* K3: assemble dense L into compensated (hi,lo) fp32                   */
/* ------------------------------------------------------------------ */
__global__ __launch_bounds__(256) void k_assemble()
{
    int i     = blockIdx.x;
    int cloud = blockIdx.y;
    __shared__ float         sX[NODES][S];
    __shared__ unsigned char sadj[NODES];
    __shared__ double        sdiag[64];
    int t = threadIdx.x;
    for (int idx = t; idx < NODES * S; idx += 256)
        ((float*)sX)[idx] = ((const float*)g_X[cloud])[idx];
    for (int idx = t; idx < NODES; idx += 256)
        sadj[idx] = g_adj[cloud][i][idx];
    __syncthreads();

    if (t < 64) {
        int    a  = t >> 3, bb = t & 7;
        double acc = 0.0;
        int    deg = 0;
        for (int k = 0; k < NODES; k++) {
            if (!sadj[k]) continue;
            deg++;
            if (k < i) {
                double d[S];
                double dn2 = 0.0;
                #pragma unroll
                for (int c = 0; c < S; c++) {
                    d[c] = (double)sX[i][c] - (double)sX[k][c];
                    dn2 += d[c] * d[c];
                }
                double dn    = sqrt(dn2) + 1e-12;
                double alpha = fmin(dn, 1.0);
                double coef  = (2.0 * alpha - alpha * alpha) / (dn * dn);
                acc -= coef * d[a] * d[bb];
            }
        }
        if (a == bb) acc += (double)deg;
        sdiag[t] = acc;
    }
    __syncthreads();

    int   a    = t >> 5;
    int   lane = t & 31;
    float2* rowp = g_A[cloud] + (size_t)(8 * i + a) * NN;
    for (int cb = 0; cb < NN; cb += 32) {
        int col = cb + lane;
        int j   = col >> 3, bb = col & 7;
        double val = 0.0;
        if (j == i) {
            val = sdiag[a * 8 + bb];
        } else if (sadj[j]) {
            double d[S];
            double dn2 = 0.0;
            #pragma unroll
            for (int c = 0; c < S; c++) {
                d[c] = (double)sX[j][c] - (double)sX[i][c];
                dn2 += d[c] * d[c];
            }
            double dn    = sqrt(dn2) + 1e-12;
            double alpha = fmin(dn, 1.0);
            double sc    = alpha / (dn * dn);
            val = sc * d[a] * d[bb] - (a == bb ? 1.0 : 0.0);
        }
        float hi = (float)val;
        float lo = (float)(val - (double)hi);
        rowp[col] = make_float2(hi, lo);
    }
}

/* ------------------------------------------------------------------ */
/* K4: persistent fused mixed-precision Householder tridiagonalization  */
/* fp32 bulk (EFT storage + Kahan dots), fp64 scalars.                  */
/* grid 2*NB blocks, TPB threads; dynamic smem = 3*NN floats            */
/* ------------------------------------------------------------------ */
__global__ __launch_bounds__(TPB, 2) void k_tridiag()
{
    extern __shared__ float fsm[];
    float* sv  = fsm;             /* v_j                         */
    float* sw  = fsm + NN;        /* w_j                         */
    float* svn = fsm + 2 * NN;    /* virtual row j+1 -> v_{j+1}  */
    __shared__ double sred[TPB / 32];
    __shared__ double s_alpha, s_norm2;

    int mat  = blockIdx.x / NB;
    int blk  = blockIdx.x % NB;
    int tid  = threadIdx.x;
    int lane = tid & 31;
    int wid  = tid >> 5;
    int gw   = blk * (TPB / 32) + wid;
    float2* A = g_A[mat];

    for (int i = blk * TPB + tid; i < NN; i += NB * TPB)
        g_vty[mat][i] = 0.0;
    gridbar(mat);

    /* ---------------- init: reflector 0 ---------------- */
    for (int t = tid; t < NN; t += TPB)
        svn[t] = __fadd_rn(A[t].x, A[t].y);
    __syncthreads();
    {
        double p = 0.0;
        for (int t = tid; t < NN; t += TPB)
            if (t >= 2) p += (double)svn[t] * (double)svn[t];
        #pragma unroll
        for (int o = 16; o; o >>= 1) p += __shfl_xor_sync(~0u, p, o);
        if (lane == 0) sred[wid] = p;
        __syncthreads();
        if (tid == 0) {
            double s = 0.0;
            for (int i = 0; i < TPB / 32; i++) s += sred[i];
            s_norm2 = s;
            s_alpha = (double)svn[1];
            if (blk == 0) g_diag[mat][0] = (double)svn[0];
        }
        __syncthreads();
        double a2  = s_alpha, n22 = s_norm2;
        double sc2 = (n22 == 0.0) ? 0.0
                   : 1.0 / (a2 + copysign(sqrt(a2 * a2 + n22), a2));
        float sc2f_hiprec;   /* scale in double, round each element */
        (void)sc2f_hiprec;
        for (int t = tid; t < NN; t += TPB)
            if (t >= 2) svn[t] = (float)((double)svn[t] * sc2);
        if (tid == 0) { svn[1] = 1.0f; svn[0] = 0.0f; }
        __syncthreads();
    }
    /* y_0 = A(1..,1..) * v_0 ; vty_0 */
    {
        double vtyp = 0.0;
        for (int q = 1 + gw; q < NN; q += NWT) {
            const float2* Ar = A + (size_t)q * NN;
            float s = 0.f, cc = 0.f;
            for (int t = lane; t < NN; t += 32) {
                float2 a = Ar[t];
                float  p = __fmaf_rn(a.y, svn[t], __fmul_rn(a.x, svn[t]));
                KH(s, cc, p);
            }
            double y = (double)s + (double)cc;
            #pragma unroll
            for (int o = 16; o; o >>= 1) y += __shfl_xor_sync(~0u, y, o);
            if (lane == 0) {
                g_y[mat][q - 1] = (float)y;
                vtyp += (double)svn[q] * y;
            }
        }
        if (lane == 0) sred[wid] = vtyp;
        __syncthreads();
        if (tid == 0) {
            double s = 0.0;
            for (int i = 0; i < TPB / 32; i++) s += sred[i];
            atomicAdd(&g_vty[mat][0], s);
        }
        __syncthreads();
        for (int t = tid; t < NN - 1; t += TPB) sv[t] = svn[t + 1];
    }
    gridbar(mat);

    /* ---------------- main loop, 1 barrier/step ---------------- */
    for (int j = 0; j + 2 < NN; ++j) {
        int m = NN - 1 - j;

        /* (a) reflector-j scalars in fp64 (identical across blocks) */
        double alpha = s_alpha, n2 = s_norm2;
        double vty = g_vty[mat][j];
        double tau, beta;
        if (n2 == 0.0) { tau = 0.0; beta = alpha; }
        else {
            beta = -copysign(sqrt(alpha * alpha + n2), alpha);
            tau  = (beta - alpha) / beta;
        }
        if (blk == 0 && tid == 0) g_offd[mat][j] = beta;
        double c2 = 0.5 * tau * tau * vty;

        /* (b) w_j = tau*y - c2*v  (fp64 form, fp32 store) */
        const float* yg = g_y[mat];
        for (int t = tid; t < m; t += TPB)
            sw[t] = (float)(tau * (double)yg[t] - c2 * (double)sv[t]);
        __syncthreads();

        /* (c) virtual update of row j+1 */
        {
            const float2* rj1 = A + (size_t)(j + 1) * NN + (j + 1);
            float v0 = sv[0], w0 = sw[0];
            for (int t = tid; t < m; t += TPB) {
                float2 a = rj1[t];
                float  r = __fadd_rn(a.x, a.y);
                svn[t] = __fsub_rn(__fsub_rn(r, __fmul_rn(v0, sw[t])),
                                   __fmul_rn(w0, sv[t]));
            }
        }
        __syncthreads();

        /* (d) reflector-(j+1) scalars from virtual row */
        {
            double p = 0.0;
            for (int t = tid; t < m; t += TPB)
                if (t >= 2) p += (double)svn[t] * (double)svn[t];
            #pragma unroll
            for (int o = 16; o; o >>= 1) p += __shfl_xor_sync(~0u, p, o);
            if (lane == 0) sred[wid] = p;
            __syncthreads();
            if (tid == 0) {
                double s = 0.0;
                for (int i = 0; i < TPB / 32; i++) s += sred[i];
                s_norm2 = s;
                s_alpha = (double)svn[1];
                if (blk == 0) g_diag[mat][j + 1] = (double)svn[0];
            }
            __syncthreads();
        }

        /* (e) v_{j+1} in svn */
        {
            double a2  = s_alpha, n22 = s_norm2;
            double sc2 = (n22 == 0.0) ? 0.0
                       : 1.0 / (a2 + copysign(sqrt(a2 * a2 + n22), a2));
            for (int t = tid; t < m; t += TPB)
                if (t >= 2) svn[t] = (float)((double)svn[t] * sc2);
            if (tid == 0) { svn[1] = 1.0f; svn[0] = 0.0f; }
            __syncthreads();
        }

        /* (f) fused sweep: EFT rank-2 update + Kahan dot with v_{j+1} */
        {
            double vtyp = 0.0;
            for (int q = 1 + gw; q < m; q += NWT) {
                float vr = sv[q], wr = sw[q];
                float2* Ar = A + (size_t)(j + 1 + q) * NN + (j + 1);
                float s = 0.f, cc = 0.f;

#define UPDT(T) do {                                                        \
    float2 a   = Ar[(T)];                                                   \
    float  dl  = __fmaf_rn(-vr, sw[(T)], __fmul_rn(-wr, sv[(T)]));          \
    float  d2  = __fadd_rn(dl, a.y);                                        \
    float  hi  = __fadd_rn(a.x, d2);                                        \
    float  bp  = __fsub_rn(hi, a.x);                                        \
    float  ap  = __fsub_rn(hi, bp);                                         \
    float  lo  = __fadd_rn(__fsub_rn(a.x, ap), __fsub_rn(d2, bp));          \
    Ar[(T)] = make_float2(hi, lo);                                          \
    float  p   = __fmaf_rn(lo, svn[(T)], __fmul_rn(hi, svn[(T)]));          \
    KH(s, cc, p);                                                           \
} while (0)

                int t = lane;
                for (; t + 96 < m; t += 128) {
                    UPDT(t);
                    UPDT(t + 32);
                    UPDT(t + 64);
                    UPDT(t + 96);
                }
                for (; t < m; t += 32) UPDT(t);
#undef UPDT

                double y = (double)s + (double)cc;
                #pragma unroll
                for (int o = 16; o; o >>= 1) y += __shfl_xor_sync(~0u, y, o);
                if (lane == 0) {
                    g_y[mat][q - 1] = (float)y;
                    vtyp += (double)svn[q] * y;
                }
            }
            if (lane == 0) sred[wid] = vtyp;
            __syncthreads();
            if (tid == 0) {
                double s = 0.0;
                for (int i = 0; i < TPB / 32; i++) s += sred[i];
                atomicAdd(&g_vty[mat][j + 1], s);
            }
            __syncthreads();
        }

        /* (g) carry v_{j+1} into sv */
        for (int t = tid; t < m - 1; t += TPB) sv[t] = svn[t + 1];
        gridbar(mat);
    }

    /* tail */
    if (blk == 0 && tid == 0) {
        g_offd[mat][NN - 2] = s_alpha;
        g_offd[mat][NN - 1] = 0.0;
        float2 last = A[(size_t)(NN - 1) * NN + (NN - 1)];
        g_diag[mat][NN - 1] = (double)last.x + (double)last.y;
    }
}

/* ------------------------------------------------------------------ */
/* K5: Sturm bisection (fp32), all 4096 eigenvalues per matrix          */
/* ------------------------------------------------------------------ */
__global__ __launch_bounds__(256) void k_bisect()
{
    int mat = blockIdx.y;
    __shared__ float sa[NN];
    __shared__ float sb2[NN];
    __shared__ float red[256];
    __shared__ float s_gl, s_gu, s_pm;
    int t = threadIdx.x;
    for (int i = t; i < NN; i += 256) {
        sa[i] = (float)g_diag[mat][i];
        float b = (i < NN - 1) ? (float)g_offd[mat][i] : 0.f;
        sb2[i] = b * b;
    }
    __syncthreads();

    float lo = 3.4e38f, hi = -3.4e38f, mb2 = 0.f;
    for (int i = t; i < NN; i += 256) {
        float bl = (i > 0)      ? sqrtf(sb2[i - 1]) : 0.f;
        float br = (i < NN - 1) ? sqrtf(sb2[i])     : 0.f;
        lo  = fminf(lo, sa[i] - bl - br);
        hi  = fmaxf(hi, sa[i] + bl + br);
        mb2 = fmaxf(mb2, sb2[i]);
    }
    red[t] = lo;  __syncthreads();
    for (int off = 128; off; off >>= 1) { if (t < off) red[t] = fminf(red[t], red[t + off]); __syncthreads(); }
    if (t == 0) s_gl = red[0];
    __syncthreads();
    red[t] = hi;  __syncthreads();
    for (int off = 128; off; off >>= 1) { if (t < off) red[t] = fmaxf(red[t], red[t + off]); __syncthreads(); }
    if (t == 0) s_gu = red[0];
    __syncthreads();
    red[t] = mb2; __syncthreads();
    for (int off = 128; off; off >>= 1) { if (t < off) red[t] = fmaxf(red[t], red[t + off]); __syncthreads(); }
    if (t == 0) s_pm = red[0];
    __syncthreads();

    float span   = s_gu - s_gl;
    float gl     = s_gl - 0.01f * span - 1e-3f;
    float gu     = s_gu + 0.01f * span + 1e-3f;
    float pivmin = fmaxf(s_pm * 1.2e-38f, 1.2e-38f);

    int tgt = blockIdx.x * 256 + t;
    float blo = gl, bhi = gu;
    for (int it = 0; it < 32; it++) {
        float mid = 0.5f * (blo + bhi);
        if (mid <= blo || mid >= bhi) break;
        float d   = sa[0] - mid;
        int   cnt = (d < 0.f);
        #pragma unroll 8
        for (int i = 1; i < NN; i++) {
            d = (sa[i] - mid) - __fdividef(sb2[i - 1], d);
            if (fabsf(d) < pivmin) d = -pivmin;
            cnt += (d < 0.f);
        }
        if (cnt > tgt) bhi = mid; else blo = mid;
    }
    g_eig[mat][tgt] = 0.5f * (blo + bhi);
}

/* ------------------------------------------------------------------ */
/* K6: spectral gaps -> triplet loss scalar (fp64)                      */
/* ------------------------------------------------------------------ */
__global__ __launch_bounds__(256) void k_final(float* __restrict__ out)
{
    __shared__ double sn[256], sd_[256];
    double gap[2];
    int t = threadIdx.x;
    for (int mat = 0; mat < 2; mat++) {
        double accn = 0.0, accd = 0.0;
        for (int i = t; i < NN; i += 256) {
            double lam = (double)fmaxf(g_eig[mat][i], 0.f);
            double z   = (lam - 1e-4) / 0.01;
            double s   = 1.0 / (1.0 + exp(-z));
            accn += lam * s;
            accd += s;
        }
        sn[t] = accn; sd_[t] = accd;
        __syncthreads();
        for (int off = 128; off; off >>= 1) {
            if (t < off) { sn[t] += sn[t + off]; sd_[t] += sd_[t + off]; }
            __syncthreads();
        }
        gap[mat] = sn[0] / (sd_[0] + 1e-12);
        __syncthreads();
    }
    if (t == 0) {
        double trip = gap[0] - gap[1] + 0.5;
        if (trip < 0.0) trip = 0.0;
        out[0] = (float)(trip + 0.1 * gap[0]);
    }
}

/* ------------------------------------------------------------------ */
extern "C" void kernel_launch(void* const* d_in, const int* in_sizes, int n_in,
                              void* d_out, int out_size)
{
    const float* q   = (const float*)d_in[0];
    const float* pos = (const float*)d_in[1];
    const float* neg = (const float*)d_in[2];
    const float* W   = (const float*)d_in[3];
    (void)in_sizes; (void)n_in; (void)out_size;

    cudaFuncSetAttribute((const void*)k_tridiag,
                         cudaFuncAttributeMaxDynamicSharedMemorySize,
                         (int)(3 * NN * sizeof(float)));

    k_proj<<<1024, 256>>>(q, pos, neg, W);
    k_knn<<<1024, 256>>>();
    {
        dim3 ga(512, 2);
        k_assemble<<<ga, 256>>>();
    }
    k_tridiag<<<2 * NB, TPB, 3 * NN * sizeof(float)>>>();
    {
        dim3 gb(16, 2);
        k_bisect<<<gb, 256>>>();
    }
    k_final<<<1, 256>>>((float*)d_out);
}